// round 1
// baseline (speedup 1.0000x reference)
#include <cuda_runtime.h>

#define NT      250000
#define NNODES  20000
#define RPW     8
#define EMB     64
#define NC      16
#define NRP     (NNODES*RPW)

// ---------------- scratch (device globals; no allocation allowed) ----------
__device__ __align__(16) float g_l1[NT*RPW];   // l1 then l1n in-place
__device__ __align__(16) float g_l2[NT*RPW];   // l2 then l2n in-place
__device__ float g_colsum[NRP];
__device__ float g_rowsum[NRP];
__device__ __align__(16) float g_h[NNODES*EMB];
__device__ int g_cnt_s[NNODES];
__device__ int g_cnt_o[NNODES];
__device__ int g_off_s[NNODES+1];
__device__ int g_off_o[NNODES+1];
__device__ int g_cur_s[NNODES];
__device__ int g_cur_o[NNODES];
__device__ int g_perm_s[NT];
__device__ int g_perm_o[NT];

// ---------------- K0: zero counters/sums, init logits with bias2 -----------
__global__ void k0_init(float* __restrict__ out, const float* __restrict__ bias2) {
    int i = blockIdx.x * blockDim.x + threadIdx.x;
    int stride = gridDim.x * blockDim.x;
    for (int j = i; j < NRP; j += stride) { g_colsum[j] = 0.f; g_rowsum[j] = 0.f; }
    for (int j = i; j < NNODES; j += stride) { g_cnt_s[j] = 0; g_cnt_o[j] = 0; }
    for (int j = i; j < NNODES*NC; j += stride) out[j] = bias2[j & (NC-1)];
}

// ---------------- K1: l1 = rm@Wl1+b1 ; l2 = softmax(rm@Wl2+b2) -------------
// 4 rows per thread so each shared weight load amortizes over 4 FMAs.
__global__ __launch_bounds__(256) void k1_l1l2(
    const float* __restrict__ rm,
    const float* __restrict__ Wl1, const float* __restrict__ bl1,
    const float* __restrict__ Wl2, const float* __restrict__ bl2)
{
    __shared__ float sW1[64*8], sW2[64*8], sb1[8], sb2[8];
    int tid = threadIdx.x;
    for (int j = tid; j < 512; j += 256) { sW1[j] = Wl1[j]; sW2[j] = Wl2[j]; }
    if (tid < 8) { sb1[tid] = bl1[tid]; sb2[tid] = bl2[tid]; }
    __syncthreads();

    const float4* rm4 = (const float4*)rm;
    int r0 = blockIdx.x * 1024 + tid;

    float a1[4][8], a2[4][8];
#pragma unroll
    for (int rr = 0; rr < 4; rr++)
#pragma unroll
        for (int p = 0; p < 8; p++) { a1[rr][p] = sb1[p]; a2[rr][p] = sb2[p]; }

    for (int k4 = 0; k4 < 16; k4++) {
        float4 x[4];
#pragma unroll
        for (int rr = 0; rr < 4; rr++) {
            int row = r0 + rr * 256;
            x[rr] = (row < NT) ? rm4[(size_t)row * 16 + k4] : make_float4(0.f,0.f,0.f,0.f);
        }
#pragma unroll
        for (int j = 0; j < 4; j++) {
            int k = k4 * 4 + j;
            float w1[8], w2[8];
#pragma unroll
            for (int p = 0; p < 8; p++) { w1[p] = sW1[k*8+p]; w2[p] = sW2[k*8+p]; }
#pragma unroll
            for (int rr = 0; rr < 4; rr++) {
                float xv = (j == 0) ? x[rr].x : (j == 1) ? x[rr].y : (j == 2) ? x[rr].z : x[rr].w;
#pragma unroll
                for (int p = 0; p < 8; p++) {
                    a1[rr][p] = fmaf(xv, w1[p], a1[rr][p]);
                    a2[rr][p] = fmaf(xv, w2[p], a2[rr][p]);
                }
            }
        }
    }

#pragma unroll
    for (int rr = 0; rr < 4; rr++) {
        int row = r0 + rr * 256;
        if (row >= NT) continue;
        // softmax over a2
        float m = a2[rr][0];
#pragma unroll
        for (int p = 1; p < 8; p++) m = fmaxf(m, a2[rr][p]);
        float e[8], s = 0.f;
#pragma unroll
        for (int p = 0; p < 8; p++) { e[p] = __expf(a2[rr][p] - m); s += e[p]; }
        float inv = 1.f / s;
        float4* d1 = (float4*)(g_l1 + (size_t)row * 8);
        float4* d2 = (float4*)(g_l2 + (size_t)row * 8);
        d1[0] = make_float4(a1[rr][0], a1[rr][1], a1[rr][2], a1[rr][3]);
        d1[1] = make_float4(a1[rr][4], a1[rr][5], a1[rr][6], a1[rr][7]);
        d2[0] = make_float4(e[0]*inv, e[1]*inv, e[2]*inv, e[3]*inv);
        d2[1] = make_float4(e[4]*inv, e[5]*inv, e[6]*inv, e[7]*inv);
    }
}

// ---------------- K2: histograms of s and o --------------------------------
__global__ void k2_hist(const int* __restrict__ hrow, const int* __restrict__ vcol) {
    int i = blockIdx.x * blockDim.x + threadIdx.x;
    int stride = gridDim.x * blockDim.x;
    for (int t = i; t < NT; t += stride) {
        atomicAdd(&g_cnt_s[hrow[t]], 1);
        atomicAdd(&g_cnt_o[vcol[t]], 1);
    }
}

// ---------------- K3: exclusive scan (one block per array) -----------------
__global__ __launch_bounds__(1024) void k3_scan() {
    const int* cnt = (blockIdx.x == 0) ? g_cnt_s : g_cnt_o;
    int* off = (blockIdx.x == 0) ? g_off_s : g_off_o;
    int* cur = (blockIdx.x == 0) ? g_cur_s : g_cur_o;
    int tid = threadIdx.x;
    const int CH = 20;                      // 1024*20 = 20480 >= 20000
    int base = tid * CH;
    int loc[CH]; int sum = 0;
#pragma unroll
    for (int j = 0; j < CH; j++) {
        int idx = base + j;
        int v = (idx < NNODES) ? cnt[idx] : 0;
        loc[j] = v; sum += v;
    }
    __shared__ int tmp[1024];
    tmp[tid] = sum; __syncthreads();
    for (int d = 1; d < 1024; d <<= 1) {
        int v = (tid >= d) ? tmp[tid - d] : 0;
        __syncthreads();
        tmp[tid] += v;
        __syncthreads();
    }
    int run = tmp[tid] - sum;               // exclusive
#pragma unroll
    for (int j = 0; j < CH; j++) {
        int idx = base + j;
        if (idx < NNODES) { off[idx] = run; cur[idx] = run; run += loc[j]; }
    }
    if (tid == 1023) off[NNODES] = tmp[1023];
}

// ---------------- K4: scatter edge ids into CSR ----------------------------
__global__ void k4_scatter(const int* __restrict__ hrow, const int* __restrict__ vcol) {
    int i = blockIdx.x * blockDim.x + threadIdx.x;
    int stride = gridDim.x * blockDim.x;
    for (int t = i; t < NT; t += stride) {
        int p1 = atomicAdd(&g_cur_s[hrow[t]], 1); g_perm_s[p1] = t;
        int p2 = atomicAdd(&g_cur_o[vcol[t]], 1); g_perm_o[p2] = t;
    }
}

// ---------------- K5: colsum (by o) and rowsum (by s), warp per node -------
__global__ __launch_bounds__(256) void k5_sums() {
    int w = (blockIdx.x * blockDim.x + threadIdx.x) >> 5;
    if (w >= 2 * NNODES) return;
    int lane = threadIdx.x & 31;
    int node, beg, end; const int* perm; const float* val; float* dst;
    if (w < NNODES) {  // s-node -> rowsum from l2
        node = w; beg = g_off_s[node]; end = g_off_s[node+1];
        perm = g_perm_s; val = g_l2; dst = g_rowsum;
    } else {           // o-node -> colsum from l1
        node = w - NNODES; beg = g_off_o[node]; end = g_off_o[node+1];
        perm = g_perm_o; val = g_l1; dst = g_colsum;
    }
    int p = lane & 7, es = lane >> 3;       // 4 edges x 8 p per iter
    float acc = 0.f;
    for (int i = beg + es; i < end; i += 4) acc += val[(size_t)perm[i]*8 + p];
    acc += __shfl_down_sync(0xffffffffu, acc, 16);
    acc += __shfl_down_sync(0xffffffffu, acc, 8);
    if (lane < 8) atomicAdd(&dst[node * lane], acc);   // index node*p
}

// ---------------- K5b: normalize l1, l2 in place ---------------------------
__global__ void k5b_norm(const int* __restrict__ hrow, const int* __restrict__ vcol) {
    int i = blockIdx.x * blockDim.x + threadIdx.x;
    int stride = gridDim.x * blockDim.x;
    float cs0 = g_colsum[0];
    float rs0 = fmaxf(g_rowsum[0], 1e-6f);
    for (int t = i; t < NT; t += stride) {
        int o = vcol[t], s = hrow[t];
        float4* l1p = (float4*)(g_l1 + (size_t)t*8);
        float4* l2p = (float4*)(g_l2 + (size_t)t*8);
        float4 a = l1p[0], b = l1p[1], c = l2p[0], d = l2p[1];
        a.x /= cs0;
        a.y /= g_colsum[o];
        a.z /= g_colsum[o*2];
        a.w /= g_colsum[o*3];
        b.x /= g_colsum[o*4];
        b.y /= g_colsum[o*5];
        b.z /= g_colsum[o*6];
        b.w /= g_colsum[o*7];
        c.x /= rs0;
        c.y /= fmaxf(g_rowsum[s],   1e-6f);
        c.z /= fmaxf(g_rowsum[s*2], 1e-6f);
        c.w /= fmaxf(g_rowsum[s*3], 1e-6f);
        d.x /= fmaxf(g_rowsum[s*4], 1e-6f);
        d.y /= fmaxf(g_rowsum[s*5], 1e-6f);
        d.z /= fmaxf(g_rowsum[s*6], 1e-6f);
        d.w /= fmaxf(g_rowsum[s*7], 1e-6f);
        l1p[0] = a; l1p[1] = b; l2p[0] = c; l2p[1] = d;
    }
}

// ---------------- K6: h[s] = relu(bias1 + sum_{t,p} l1n * W1[o*p]) ---------
// one block per s-node, 64 threads = EMB; no atomics.
__global__ __launch_bounds__(64) void k6_h(
    const int* __restrict__ vcol, const float* __restrict__ W1,
    const float* __restrict__ bias1)
{
    int s = blockIdx.x, e = threadIdx.x;
    int beg = g_off_s[s], end = g_off_s[s+1];
    float acc = 0.f;
    __shared__ int sh_t[64], sh_o[64];
    for (int tile = beg; tile < end; tile += 64) {
        int n = min(64, end - tile);
        if (e < n) { int t = g_perm_s[tile + e]; sh_t[e] = t; sh_o[e] = vcol[t]; }
        __syncthreads();
        for (int i = 0; i < n; i++) {
            int t = sh_t[i], o = sh_o[i];
            const float4* ln = (const float4*)(g_l1 + (size_t)t*8);
            float4 wa = ln[0], wb = ln[1];
            int ob = o * 64;
            acc = fmaf(wa.x, __ldg(&W1[e]),          acc);  // p=0 -> row 0
            acc = fmaf(wa.y, __ldg(&W1[ob     + e]), acc);
            acc = fmaf(wa.z, __ldg(&W1[ob*2   + e]), acc);
            acc = fmaf(wa.w, __ldg(&W1[ob*3   + e]), acc);
            acc = fmaf(wb.x, __ldg(&W1[ob*4   + e]), acc);
            acc = fmaf(wb.y, __ldg(&W1[ob*5   + e]), acc);
            acc = fmaf(wb.z, __ldg(&W1[ob*6   + e]), acc);
            acc = fmaf(wb.w, __ldg(&W1[ob*7   + e]), acc);
        }
        __syncthreads();
    }
    g_h[(size_t)s*64 + e] = fmaxf(acc + bias1[e], 0.f);
}

// ---------------- K7: fused h2 + einsum -> logits --------------------------
// per s-node: contrib_p = sum_t l2n[t,p]*h[o_t]; logits[(s*p)%N] += contrib_p @ W2[(s*p)/N]
__global__ __launch_bounds__(64) void k7_logits(
    const int* __restrict__ vcol, const float* __restrict__ W2,
    float* __restrict__ out)
{
    int s = blockIdx.x, tid = threadIdx.x;
    int beg = g_off_s[s], end = g_off_s[s+1];
    if (beg == end) return;
    float a0=0,a1=0,a2=0,a3=0,a4=0,a5=0,a6=0,a7=0;
    __shared__ int sh_t[64], sh_o[64];
    for (int tile = beg; tile < end; tile += 64) {
        int n = min(64, end - tile);
        if (tid < n) { int t = g_perm_s[tile + tid]; sh_t[tid] = t; sh_o[tid] = vcol[t]; }
        __syncthreads();
        for (int i = 0; i < n; i++) {
            int t = sh_t[i], o = sh_o[i];
            float hv = g_h[(size_t)o*64 + tid];
            const float4* ln = (const float4*)(g_l2 + (size_t)t*8);
            float4 la = ln[0], lb = ln[1];
            a0 = fmaf(la.x, hv, a0); a1 = fmaf(la.y, hv, a1);
            a2 = fmaf(la.z, hv, a2); a3 = fmaf(la.w, hv, a3);
            a4 = fmaf(lb.x, hv, a4); a5 = fmaf(lb.y, hv, a5);
            a6 = fmaf(lb.z, hv, a6); a7 = fmaf(lb.w, hv, a7);
        }
        __syncthreads();
    }
    __shared__ float sh1[8][64];
    sh1[0][tid]=a0; sh1[1][tid]=a1; sh1[2][tid]=a2; sh1[3][tid]=a3;
    sh1[4][tid]=a4; sh1[5][tid]=a5; sh1[6][tid]=a6; sh1[7][tid]=a7;
    __syncthreads();
    int g = tid >> 4, c = tid & 15;
    float part[8];
#pragma unroll
    for (int p = 0; p < 8; p++) {
        int q = s * p; int r = q / NNODES;
        const float* w2 = W2 + r * (EMB*NC);
        float y = 0.f;
#pragma unroll
        for (int hh = 0; hh < 16; hh++)
            y = fmaf(sh1[p][g*16 + hh], __ldg(&w2[(g*16 + hh)*16 + c]), y);
        part[p] = y;
    }
    __shared__ float sh2[8][64];
#pragma unroll
    for (int p = 0; p < 8; p++) sh2[p][tid] = part[p];
    __syncthreads();
#pragma unroll
    for (int pp = g; pp < 8; pp += 4) {
        float y = sh2[pp][c] + sh2[pp][16+c] + sh2[pp][32+c] + sh2[pp][48+c];
        int q = s * pp; int n_ = q - (q / NNODES) * NNODES;
        atomicAdd(&out[n_*NC + c], y);
    }
}

// ---------------- launch ----------------------------------------------------
extern "C" void kernel_launch(void* const* d_in, const int* in_sizes, int n_in,
                              void* d_out, int out_size) {
    const float* rm    = (const float*)d_in[0];
    const int*   hrow  = (const int*)  d_in[1];   // first NT entries = s[t]
    const int*   vcol  = (const int*)  d_in[4];   // first NT entries = o[t]
    const float* Wl1   = (const float*)d_in[5];
    const float* bl1   = (const float*)d_in[6];
    const float* Wl2   = (const float*)d_in[7];
    const float* bl2   = (const float*)d_in[8];
    const float* W1    = (const float*)d_in[9];
    const float* W2    = (const float*)d_in[10];
    const float* bias1 = (const float*)d_in[11];
    const float* bias2 = (const float*)d_in[12];
    float* out = (float*)d_out;

    k0_init   <<<256, 256>>>(out, bias2);
    k1_l1l2   <<<(NT + 1023) / 1024, 256>>>(rm, Wl1, bl1, Wl2, bl2);
    k2_hist   <<<256, 256>>>(hrow, vcol);
    k3_scan   <<<2, 1024>>>();
    k4_scatter<<<256, 256>>>(hrow, vcol);
    k5_sums   <<<(2*NNODES*32 + 255) / 256, 256>>>();
    k5b_norm  <<<256, 256>>>(hrow, vcol);
    k6_h      <<<NNODES, 64>>>(vcol, W1, bias1);
    k7_logits <<<NNODES, 64>>>(vcol, W2, out);
}

// round 2
// speedup vs baseline: 1.3990x; 1.3990x over previous
#include <cuda_runtime.h>

#define NT      250000
#define NNODES  20000
#define EMB     64
#define NC      16
#define NRP     (NNODES*8)

// ---------------- scratch ---------------------------------------------------
__device__ __align__(16) float g_l1[NT*8];       // raw l1
__device__ __align__(16) float g_l2[NT*8];       // softmaxed l2
__device__ float g_colsum[NRP];
__device__ float g_rowsum[NRP];
__device__ __align__(16) float g_invC[NRP];      // [o][p] = 1/colsum[o*p]
__device__ __align__(16) float g_invR[NRP];      // [s][p] = 1/max(rowsum[s*p],1e-6)
__device__ __align__(16) float g_h[NNODES*EMB];
__device__ int   g_cnt_s[NNODES];
__device__ int   g_off_s[NNODES+1];
__device__ int   g_cur_s[NNODES];
__device__ int   g_perm_s[NT];
__device__ float g_out0[64*16];                  // striped partials for p=0 logits

// ---------------- K0: zero everything + init logits with bias2 --------------
__global__ void k0_init(float* __restrict__ out, const float* __restrict__ bias2) {
    int i = blockIdx.x * blockDim.x + threadIdx.x;
    int stride = gridDim.x * blockDim.x;
    for (int j = i; j < NRP; j += stride) { g_colsum[j] = 0.f; g_rowsum[j] = 0.f; }
    for (int j = i; j < NNODES; j += stride) g_cnt_s[j] = 0;
    for (int j = i; j < NNODES*NC; j += stride) out[j] = bias2[j & (NC-1)];
    for (int j = i; j < 64*16; j += stride) g_out0[j] = 0.f;
}

// ---------------- K1: GEMMs + softmax + colsum/rowsum atomics + s-hist ------
__global__ __launch_bounds__(256) void k1_l1l2(
    const float* __restrict__ rm,
    const float* __restrict__ Wl1, const float* __restrict__ bl1,
    const float* __restrict__ Wl2, const float* __restrict__ bl2,
    const int* __restrict__ hrow, const int* __restrict__ vcol)
{
    __shared__ float sW1[64*8], sW2[64*8], sb1[8], sb2[8];
    int tid = threadIdx.x;
    for (int j = tid; j < 512; j += 256) { sW1[j] = Wl1[j]; sW2[j] = Wl2[j]; }
    if (tid < 8) { sb1[tid] = bl1[tid]; sb2[tid] = bl2[tid]; }
    __syncthreads();

    const float4* rm4 = (const float4*)rm;
    int r0 = blockIdx.x * 1024 + tid;

    float a1[4][8], a2[4][8];
#pragma unroll
    for (int rr = 0; rr < 4; rr++)
#pragma unroll
        for (int p = 0; p < 8; p++) { a1[rr][p] = sb1[p]; a2[rr][p] = sb2[p]; }

    for (int k4 = 0; k4 < 16; k4++) {
        float4 x[4];
#pragma unroll
        for (int rr = 0; rr < 4; rr++) {
            int row = r0 + rr * 256;
            x[rr] = (row < NT) ? rm4[(size_t)row * 16 + k4] : make_float4(0.f,0.f,0.f,0.f);
        }
#pragma unroll
        for (int j = 0; j < 4; j++) {
            int k = k4 * 4 + j;
            float w1[8], w2[8];
#pragma unroll
            for (int p = 0; p < 8; p++) { w1[p] = sW1[k*8+p]; w2[p] = sW2[k*8+p]; }
#pragma unroll
            for (int rr = 0; rr < 4; rr++) {
                float xv = (j == 0) ? x[rr].x : (j == 1) ? x[rr].y : (j == 2) ? x[rr].z : x[rr].w;
#pragma unroll
                for (int p = 0; p < 8; p++) {
                    a1[rr][p] = fmaf(xv, w1[p], a1[rr][p]);
                    a2[rr][p] = fmaf(xv, w2[p], a2[rr][p]);
                }
            }
        }
    }

    float p0l1 = 0.f, p0l2 = 0.f;
#pragma unroll
    for (int rr = 0; rr < 4; rr++) {
        int row = r0 + rr * 256;
        if (row >= NT) continue;
        float m = a2[rr][0];
#pragma unroll
        for (int p = 1; p < 8; p++) m = fmaxf(m, a2[rr][p]);
        float e[8], ssum = 0.f;
#pragma unroll
        for (int p = 0; p < 8; p++) { e[p] = __expf(a2[rr][p] - m); ssum += e[p]; }
        float inv = 1.f / ssum;
#pragma unroll
        for (int p = 0; p < 8; p++) e[p] *= inv;

        float4* d1 = (float4*)(g_l1 + (size_t)row * 8);
        float4* d2 = (float4*)(g_l2 + (size_t)row * 8);
        d1[0] = make_float4(a1[rr][0], a1[rr][1], a1[rr][2], a1[rr][3]);
        d1[1] = make_float4(a1[rr][4], a1[rr][5], a1[rr][6], a1[rr][7]);
        d2[0] = make_float4(e[0], e[1], e[2], e[3]);
        d2[1] = make_float4(e[4], e[5], e[6], e[7]);

        int o = vcol[row], s = hrow[row];
        p0l1 += a1[rr][0];
        p0l2 += e[0];
#pragma unroll
        for (int p = 1; p < 8; p++) {
            atomicAdd(&g_colsum[o * p], a1[rr][p]);
            atomicAdd(&g_rowsum[s * p], e[p]);
        }
        atomicAdd(&g_cnt_s[s], 1);
    }

    // block-reduce the p=0 contributions (all map to segment 0)
    int lane = tid & 31, wid = tid >> 5;
#pragma unroll
    for (int d = 16; d > 0; d >>= 1) {
        p0l1 += __shfl_down_sync(0xffffffffu, p0l1, d);
        p0l2 += __shfl_down_sync(0xffffffffu, p0l2, d);
    }
    __shared__ float red1[8], red2[8];
    if (lane == 0) { red1[wid] = p0l1; red2[wid] = p0l2; }
    __syncthreads();
    if (tid == 0) {
        float s1 = 0.f, s2 = 0.f;
#pragma unroll
        for (int w = 0; w < 8; w++) { s1 += red1[w]; s2 += red2[w]; }
        atomicAdd(&g_colsum[0], s1);
        atomicAdd(&g_rowsum[0], s2);
    }
}

// ---------------- K3: fast 3-level shuffle scan (s only, 1 block) -----------
__global__ __launch_bounds__(1024) void k3_scan() {
    int tid = threadIdx.x;
    const int CH = 20;                      // 1024*20 = 20480 >= 20000
    int base = tid * CH;
    int loc[CH]; int sum = 0;
#pragma unroll
    for (int j = 0; j < CH; j++) {
        int idx = base + j;
        int v = (idx < NNODES) ? g_cnt_s[idx] : 0;
        loc[j] = v; sum += v;
    }
    int lane = tid & 31, wid = tid >> 5;
    int x = sum;
#pragma unroll
    for (int d = 1; d < 32; d <<= 1) {
        int y = __shfl_up_sync(0xffffffffu, x, d);
        if (lane >= d) x += y;
    }
    __shared__ int wsum[32];
    if (lane == 31) wsum[wid] = x;
    __syncthreads();
    if (wid == 0) {
        int w = wsum[lane];
#pragma unroll
        for (int d = 1; d < 32; d <<= 1) {
            int y = __shfl_up_sync(0xffffffffu, w, d);
            if (lane >= d) w += y;
        }
        wsum[lane] = w;
    }
    __syncthreads();
    int run = x - sum + (wid ? wsum[wid - 1] : 0);   // exclusive prefix
#pragma unroll
    for (int j = 0; j < CH; j++) {
        int idx = base + j;
        if (idx < NNODES) { g_off_s[idx] = run; g_cur_s[idx] = run; run += loc[j]; }
    }
    if (tid == 1023) g_off_s[NNODES] = wsum[31];
}

// ---------------- K45: scatter edges into CSR + build inverse tables --------
__global__ void k45_scatter_inv(const int* __restrict__ hrow) {
    int i = blockIdx.x * blockDim.x + threadIdx.x;
    int stride = gridDim.x * blockDim.x;
    for (int t = i; t < NT; t += stride) {
        int p = atomicAdd(&g_cur_s[hrow[t]], 1);
        g_perm_s[p] = t;
    }
    for (int j = i; j < NRP; j += stride) {
        int node = j >> 3, p = j & 7;
        g_invC[j] = 1.f / g_colsum[node * p];
        g_invR[j] = 1.f / fmaxf(g_rowsum[node * p], 1e-6f);
    }
}

// ---------------- K6: h[s] = relu(bias1 + sum_{t,p} l1n * W1[o*p]) ----------
__global__ __launch_bounds__(64) void k6_h(
    const int* __restrict__ vcol, const float* __restrict__ W1,
    const float* __restrict__ bias1)
{
    int s = blockIdx.x, e = threadIdx.x;
    int beg = g_off_s[s], end = g_off_s[s+1];
    __shared__ float sh_l[64][9];
    __shared__ int sh_ob[64];
    float acc = 0.f, acc0 = 0.f;
    for (int tile = beg; tile < end; tile += 64) {
        int n = min(64, end - tile);
        if (e < n) {
            int t = g_perm_s[tile + e];
            int o = vcol[t];
            sh_ob[e] = o * 64;
            const float4* lp = (const float4*)(g_l1 + (size_t)t * 8);
            const float4* ip = (const float4*)(g_invC + (size_t)o * 8);
            float4 a = lp[0], b = lp[1], ia = ip[0], ib = ip[1];
            sh_l[e][0] = a.x * ia.x; sh_l[e][1] = a.y * ia.y;
            sh_l[e][2] = a.z * ia.z; sh_l[e][3] = a.w * ia.w;
            sh_l[e][4] = b.x * ib.x; sh_l[e][5] = b.y * ib.y;
            sh_l[e][6] = b.z * ib.z; sh_l[e][7] = b.w * ib.w;
        }
        __syncthreads();
        for (int i = 0; i < n; i++) {
            int ob = sh_ob[i];
            acc0 += sh_l[i][0];                              // p=0 row is W1[0..63]
            acc = fmaf(sh_l[i][1], __ldg(&W1[ob     + e]), acc);
            acc = fmaf(sh_l[i][2], __ldg(&W1[ob*2   + e]), acc);
            acc = fmaf(sh_l[i][3], __ldg(&W1[ob*3   + e]), acc);
            acc = fmaf(sh_l[i][4], __ldg(&W1[ob*4   + e]), acc);
            acc = fmaf(sh_l[i][5], __ldg(&W1[ob*5   + e]), acc);
            acc = fmaf(sh_l[i][6], __ldg(&W1[ob*6   + e]), acc);
            acc = fmaf(sh_l[i][7], __ldg(&W1[ob*7   + e]), acc);
        }
        __syncthreads();
    }
    acc = fmaf(acc0, __ldg(&W1[e]), acc);
    g_h[(size_t)s*64 + e] = fmaxf(acc + bias1[e], 0.f);
}

// ---------------- K7: fused h2 + einsum -> logits ---------------------------
__global__ __launch_bounds__(64) void k7_logits(
    const int* __restrict__ vcol, const float* __restrict__ W2,
    float* __restrict__ out)
{
    int s = blockIdx.x, tid = threadIdx.x;
    int beg = g_off_s[s], end = g_off_s[s+1];
    if (beg == end) return;
    __shared__ float sh_l[64][9];
    __shared__ int sh_o[64];
    float a[8] = {0.f,0.f,0.f,0.f,0.f,0.f,0.f,0.f};
    const float4* ir = (const float4*)(g_invR + (size_t)s * 8);
    float4 ia = ir[0], ib = ir[1];
    for (int tile = beg; tile < end; tile += 64) {
        int n = min(64, end - tile);
        if (tid < n) {
            int t = g_perm_s[tile + tid];
            int o = vcol[t];
            sh_o[tid] = o;
            const float4* lp = (const float4*)(g_l2 + (size_t)t * 8);
            float4 la = lp[0], lb = lp[1];
            sh_l[tid][0] = la.x * ia.x; sh_l[tid][1] = la.y * ia.y;
            sh_l[tid][2] = la.z * ia.z; sh_l[tid][3] = la.w * ia.w;
            sh_l[tid][4] = lb.x * ib.x; sh_l[tid][5] = lb.y * ib.y;
            sh_l[tid][6] = lb.z * ib.z; sh_l[tid][7] = lb.w * ib.w;
        }
        __syncthreads();
        for (int i = 0; i < n; i++) {
            float hv = g_h[(size_t)sh_o[i]*64 + tid];
#pragma unroll
            for (int p = 0; p < 8; p++) a[p] = fmaf(sh_l[i][p], hv, a[p]);
        }
        __syncthreads();
    }
    __shared__ float sh1[8][64];
#pragma unroll
    for (int p = 0; p < 8; p++) sh1[p][tid] = a[p];
    __syncthreads();
    int g = tid >> 4, c = tid & 15;
    float part[8];
#pragma unroll
    for (int p = 0; p < 8; p++) {
        int q = s * p; int r = q / NNODES;
        const float* w2 = W2 + r * (EMB*NC);
        float y = 0.f;
#pragma unroll
        for (int hh = 0; hh < 16; hh++)
            y = fmaf(sh1[p][g*16 + hh], __ldg(&w2[(g*16 + hh)*16 + c]), y);
        part[p] = y;
    }
    __shared__ float sh2[8][64];
#pragma unroll
    for (int p = 0; p < 8; p++) sh2[p][tid] = part[p];
    __syncthreads();
#pragma unroll
    for (int pp = g; pp < 8; pp += 4) {
        float y = sh2[pp][c] + sh2[pp][16+c] + sh2[pp][32+c] + sh2[pp][48+c];
        if (pp == 0) {
            atomicAdd(&g_out0[(s & 63)*16 + c], y);     // striped: kills 20000-way contention
        } else {
            int q = s * pp; int n_ = q - (q / NNODES) * NNODES;
            atomicAdd(&out[n_*NC + c], y);
        }
    }
}

// ---------------- K8: fold striped p=0 partials into logits row 0 -----------
__global__ void k8_reduce(float* __restrict__ out) {
    int c = threadIdx.x;            // 16 threads
    if (c >= 16) return;
    float sum = 0.f;
#pragma unroll
    for (int k = 0; k < 64; k++) sum += g_out0[k*16 + c];
    out[c] += sum;                  // runs after k7; single writer
}

// ---------------- launch ----------------------------------------------------
extern "C" void kernel_launch(void* const* d_in, const int* in_sizes, int n_in,
                              void* d_out, int out_size) {
    const float* rm    = (const float*)d_in[0];
    const int*   hrow  = (const int*)  d_in[1];   // first NT entries = s[t]
    const int*   vcol  = (const int*)  d_in[4];   // first NT entries = o[t]
    const float* Wl1   = (const float*)d_in[5];
    const float* bl1   = (const float*)d_in[6];
    const float* Wl2   = (const float*)d_in[7];
    const float* bl2   = (const float*)d_in[8];
    const float* W1    = (const float*)d_in[9];
    const float* W2    = (const float*)d_in[10];
    const float* bias1 = (const float*)d_in[11];
    const float* bias2 = (const float*)d_in[12];
    float* out = (float*)d_out;

    k0_init        <<<256, 256>>>(out, bias2);
    k1_l1l2        <<<(NT + 1023) / 1024, 256>>>(rm, Wl1, bl1, Wl2, bl2, hrow, vcol);
    k3_scan        <<<1, 1024>>>();
    k45_scatter_inv<<<256, 256>>>(hrow);
    k6_h           <<<NNODES, 64>>>(vcol, W1, bias1);
    k7_logits      <<<NNODES, 64>>>(vcol, W2, out);
    k8_reduce      <<<1, 16>>>(out);
}